// round 6
// baseline (speedup 1.0000x reference)
#include <cuda_runtime.h>
#include <cuda_bf16.h>
#include <cstdint>

#define L 4096
#define E 300
#define H2 256
#define NROW 1024         // 4*H2 gate rows
#define HID 512
#define T 16
#define START_TAG 14
#define STOP_TAG 15
#define NEGV (-10000.0f)

#define CSZ 8             // cluster size (CTAs per direction)
#define JPC (H2/CSZ)      // 32 h-indices per CTA
#define RPC (NROW/CSZ)    // 128 gate rows per CTA
#define LTHR 512          // threads per LSTM CTA
#define NARR (CSZ*JPC)    // 256 arrivals per phase per barrier

// ---------------- scratch (static device globals; no allocation) ----------------
__device__ float g_X[L*E];             // gathered embeddings   [4096,300]
__device__ float g_xz[2][L][NROW];     // x@W_ih^T + b          per dir
__device__ float g_hs[2][L][H2];       // hf / hb outputs
__device__ float g_feats[L*T];         // emission scores

// ---------------- helpers ----------------
__device__ __forceinline__ float sigm(float x){
    return __fdividef(1.0f, 1.0f + __expf(-x));
}
__device__ __forceinline__ float tanh_(float x){
    float ax = fabsf(x);
    float e  = __expf(-2.0f*ax);
    float t  = __fdividef(1.0f - e, 1.0f + e);
    return copysignf(t, x);
}
__device__ __forceinline__ unsigned smem_u32(const void* p){
    unsigned r;
    asm("{ .reg .u64 t; cvta.to.shared.u64 t, %1; cvt.u32.u64 %0, t; }" : "=r"(r) : "l"(p));
    return r;
}
__device__ __forceinline__ void cluster_sync_(){
    asm volatile("barrier.cluster.arrive.aligned;" ::: "memory");
    asm volatile("barrier.cluster.wait.aligned;"   ::: "memory");
}
__device__ __forceinline__ unsigned mapa_(unsigned laddr, int rank){
    unsigned r;
    asm("mapa.shared::cluster.u32 %0, %1, %2;" : "=r"(r) : "r"(laddr), "r"(rank));
    return r;
}
__device__ __forceinline__ void mbar_init_(unsigned maddr, unsigned cnt){
    asm volatile("mbarrier.init.shared.b64 [%0], %1;" :: "r"(maddr), "r"(cnt) : "memory");
}
__device__ __forceinline__ void mbar_arrive_remote(unsigned maddr){
    asm volatile("mbarrier.arrive.release.cluster.shared::cluster.b64 _, [%0];"
                 :: "r"(maddr) : "memory");
}
__device__ __forceinline__ void mbar_wait_cluster(unsigned maddr, unsigned par){
    asm volatile(
        "{\n\t.reg .pred P;\n\t"
        "WL_%=:\n\t"
        "mbarrier.try_wait.parity.acquire.cluster.shared::cta.b64 P, [%0], %1, 0x989680;\n\t"
        "@P bra.uni WD_%=;\n\t"
        "bra.uni WL_%=;\n\t"
        "WD_%=:\n\t}"
        :: "r"(maddr), "r"(par) : "memory");
}
__device__ __forceinline__ void st_cluster_f32(unsigned daddr, float v){
    asm volatile("st.shared::cluster.f32 [%0], %1;" :: "r"(daddr), "f"(v) : "memory");
}

// ---------------- 1. gather embeddings ----------------
__global__ void gather_kernel(const int* __restrict__ sent, const float* __restrict__ emb){
    int t = blockIdx.x;
    int row = sent[t];
    for (int e = threadIdx.x; e < E; e += blockDim.x)
        g_X[t*E + e] = emb[row*E + e];
}

// ---------------- 2. xz = X @ W_ih^T + b  (both directions) ----------------
#define KT 16
__global__ void __launch_bounds__(256) xz_gemm_kernel(
    const float* __restrict__ wf, const float* __restrict__ wb,
    const float* __restrict__ bf, const float* __restrict__ bb)
{
    __shared__ float As[64][20];
    __shared__ float Bs[64][20];
    int d  = blockIdx.z;
    const float* wih  = d ? wb : wf;
    const float* bias = d ? bb : bf;
    int t0 = blockIdx.y * 64;
    int r0 = blockIdx.x * 64;
    int tid = threadIdx.x;
    int tx = tid & 15, ty = tid >> 4;
    float acc[4][4] = {};
    for (int kb = 0; kb < E; kb += KT){
        for (int idx = tid; idx < 64*KT; idx += 256){
            int row = idx >> 4, k = idx & 15;
            int kk = kb + k;
            As[row][k] = (kk < E) ? g_X[(t0+row)*E + kk]    : 0.f;
            Bs[row][k] = (kk < E) ? wih[(r0+row)*E + kk]    : 0.f;
        }
        __syncthreads();
        #pragma unroll
        for (int k4 = 0; k4 < KT; k4 += 4){
            float4 a[4], b[4];
            #pragma unroll
            for (int i=0;i<4;i++) a[i] = *(const float4*)&As[ty*4+i][k4];
            #pragma unroll
            for (int j=0;j<4;j++) b[j] = *(const float4*)&Bs[tx*4+j][k4];
            #pragma unroll
            for (int i=0;i<4;i++)
                #pragma unroll
                for (int j=0;j<4;j++)
                    acc[i][j] += a[i].x*b[j].x + a[i].y*b[j].y + a[i].z*b[j].z + a[i].w*b[j].w;
        }
        __syncthreads();
    }
    #pragma unroll
    for (int i=0;i<4;i++){
        int t = t0 + ty*4 + i;
        #pragma unroll
        for (int j=0;j<4;j++){
            int r = r0 + tx*4 + j;
            g_xz[d][t][r] = acc[i][j] + bias[r];
        }
    }
}

// ---------------- 3. sequential BiLSTM: 2 clusters of 8 CTAs ----------------
// NO cluster.sync in the step loop. h broadcast via plain DSMEM stores +
// arrive-counted mbarriers (count=256, double-buffered, parity in registers).
__global__ void __cluster_dims__(CSZ,1,1) __launch_bounds__(LTHR,1)
lstm_kernel(const float* __restrict__ w_hh_f, const float* __restrict__ w_hh_b,
            const float* __restrict__ h0, const float* __restrict__ c0)
{
    __shared__ alignas(16) float h_buf[2][H2];
    __shared__ float z_s[RPC];
    __shared__ alignas(8) unsigned long long mbars[2];

    unsigned rank;
    asm("mov.u32 %0, %%cluster_ctarank;" : "=r"(rank));
    int dir = blockIdx.x / CSZ;
    int tid  = threadIdx.x;
    int j    = tid >> 4;         // h-index within CTA for weight role (0..31)
    int sub  = tid & 15;
    int gate = sub >> 2;         // 0..3 (i,f,g,o)
    int q    = sub & 3;          // quarter of the 256-wide dot
    int grow = gate*H2 + (int)rank*JPC + j;   // global gate row

    const float* W = (dir ? w_hh_b : w_hh_f) + grow*H2 + q*64;
    unsigned long long w2[32];   // 64 weights as f32x2 pairs
    #pragma unroll
    for (int i=0;i<32;i++) w2[i] = ((const unsigned long long*)W)[i];

    // init
    for (int i = tid; i < H2; i += LTHR) h_buf[0][i] = h0[dir*H2 + i];
    float c = 0.f;
    int hidx = (int)rank*JPC + tid;          // activation role (tid<32)
    if (tid < 32) c = c0[dir*H2 + hidx];

    unsigned mb_local = smem_u32(&mbars[0]);
    if (tid == 0){
        mbar_init_(mb_local,     NARR);
        mbar_init_(mb_local + 8, NARR);
    }

    // remote addresses (used by tid<32 only, computed by all)
    unsigned ra_d[CSZ], ra_m[CSZ];
    {
        unsigned la_d = smem_u32(&h_buf[0][(tid < 32 ? hidx : 0)]);
        #pragma unroll
        for (int ct = 0; ct < CSZ; ct++){
            ra_d[ct] = mapa_(la_d, ct);
            ra_m[ct] = mapa_(mb_local, ct);
        }
    }

    const float* xz = &g_xz[dir][0][0];
    float x_cur = 0.f, x_next = 0.f;
    if (q == 0){
        int t0 = dir ? (L-1) : 0;
        x_cur = __ldg(&xz[t0*NROW + grow]);
    }

    __syncthreads();
    cluster_sync_();             // all mbars initialized before any arrive

    unsigned p0 = 0, p1 = 0;     // parity trackers for mbars[0], mbars[1]

    for (int s = 0; s < L; s++){
        int cur = s & 1;
        int nxt = cur ^ 1;
        if (s > 0){              // wait for h_buf[cur] delivery (256 arrivals)
            unsigned ma = mb_local + (unsigned)cur*8u;
            unsigned par = cur ? p1 : p0;
            mbar_wait_cluster(ma, par);
            if (cur) p1 ^= 1; else p0 ^= 1;
        }
        if (q == 0 && s + 1 < L){                // prefetch next xz
            int t1 = dir ? (L-2-s) : (s+1);
            x_next = __ldg(&xz[t1*NROW + grow]);
        }
        const ulonglong2* hp = (const ulonglong2*)&h_buf[cur][q*64];
        unsigned long long a0=0ull, a1=0ull, a2=0ull, a3=0ull;
        #pragma unroll
        for (int i=0;i<8;i++){
            ulonglong2 hA = hp[2*i];
            ulonglong2 hB = hp[2*i+1];
            asm("fma.rn.f32x2 %0, %1, %2, %0;" : "+l"(a0) : "l"(w2[4*i]),   "l"(hA.x));
            asm("fma.rn.f32x2 %0, %1, %2, %0;" : "+l"(a1) : "l"(w2[4*i+1]), "l"(hA.y));
            asm("fma.rn.f32x2 %0, %1, %2, %0;" : "+l"(a2) : "l"(w2[4*i+2]), "l"(hB.x));
            asm("fma.rn.f32x2 %0, %1, %2, %0;" : "+l"(a3) : "l"(w2[4*i+3]), "l"(hB.y));
        }
        float v = (__uint_as_float((unsigned)a0) + __uint_as_float((unsigned)(a0>>32)))
                + (__uint_as_float((unsigned)a1) + __uint_as_float((unsigned)(a1>>32)))
                + (__uint_as_float((unsigned)a2) + __uint_as_float((unsigned)(a2>>32)))
                + (__uint_as_float((unsigned)a3) + __uint_as_float((unsigned)(a3>>32)));
        v += __shfl_xor_sync(0xffffffffu, v, 1);
        v += __shfl_xor_sync(0xffffffffu, v, 2);
        if (q == 0) z_s[gate*JPC + j] = v + x_cur;
        __syncthreads();         // z staged + all h_buf[cur] reads complete
        if (tid < 32){
            float zi = z_s[tid], zf = z_s[JPC+tid], zg = z_s[2*JPC+tid], zo = z_s[3*JPC+tid];
            float ig = sigm(zi), fg = sigm(zf), og = sigm(zo);
            float gg = tanh_(zg);
            c = fg*c + ig*gg;
            float h = og * tanh_(c);
            int t_act = dir ? (L-1-s) : s;
            g_hs[dir][t_act][hidx] = h;
            if (s + 1 < L){
                unsigned doff = (unsigned)nxt * (H2*4u);
                unsigned moff = (unsigned)nxt * 8u;
                #pragma unroll
                for (int ct = 0; ct < CSZ; ct++)
                    st_cluster_f32(ra_d[ct] + doff, h);
                #pragma unroll
                for (int ct = 0; ct < CSZ; ct++)
                    mbar_arrive_remote(ra_m[ct] + moff);
            }
        }
        x_cur = x_next;
    }
    cluster_sync_();             // no CTA exits while peers may still be targeted
}

// ---------------- 4. emission features: feats = [hf|hb] @ W_out^T + b_out ----------------
__global__ void feats_kernel(const float* __restrict__ Wout, const float* __restrict__ bout){
    int gid = blockIdx.x*blockDim.x + threadIdx.x;
    int t = gid >> 4, n = gid & 15;
    const float4* hf = (const float4*)g_hs[0][t];
    const float4* hb = (const float4*)g_hs[1][t];
    const float4* w0 = (const float4*)(Wout + n*HID);
    const float4* w1 = (const float4*)(Wout + n*HID + H2);
    float acc = bout[n];
    #pragma unroll 4
    for (int k=0;k<H2/4;k++){
        float4 a = hf[k], b = w0[k];
        acc += a.x*b.x + a.y*b.y + a.z*b.z + a.w*b.w;
    }
    #pragma unroll 4
    for (int k=0;k<H2/4;k++){
        float4 a = hb[k], b = w1[k];
        acc += a.x*b.x + a.y*b.y + a.z*b.z + a.w*b.w;
    }
    g_feats[t*T + n] = acc;
}

// ---------------- 5. Viterbi + backtrack (argmax tree, backpointers in shared) ----------------
__global__ void viterbi_kernel(const float* __restrict__ trans, float* __restrict__ out,
                               int out_size){
    extern __shared__ unsigned char bp[];   // [L][T] backpointers
    int n = threadIdx.x;                    // 16 threads
    const unsigned mask = 0xffffu;
    float tr[T];
    #pragma unroll
    for (int p=0;p<T;p++) tr[p] = trans[n*T + p];   // trans[next=n][prev=p]
    float fv = (n == START_TAG) ? 0.f : NEGV;
    float f_cur = g_feats[n];
    for (int t = 0; t < L; t++){
        float f_next = (t+1 < L) ? __ldg(&g_feats[(t+1)*T + n]) : 0.f;
        float cv[T]; int ci[T];
        #pragma unroll
        for (int p=0;p<T;p++){
            cv[p] = __shfl_sync(mask, fv, p) + tr[p];
            ci[p] = p;
        }
        // argmax tree; ties keep lower index (left) => first max, matches jnp.argmax
        #pragma unroll
        for (int w=8; w>=1; w>>=1)
            #pragma unroll
            for (int p=0;p<16;p++) if (p < w){
                if (cv[p+w] > cv[p]){ cv[p] = cv[p+w]; ci[p] = ci[p+w]; }
            }
        fv = cv[0] + f_cur;
        bp[t*T + n] = (unsigned char)ci[0];
        f_cur = f_next;
    }
    float term = fv + trans[STOP_TAG*T + n];
    __syncwarp(mask);
    float bestv = -3.4e38f; int bestn = 0;
    #pragma unroll
    for (int p=0;p<T;p++){
        float v = __shfl_sync(mask, term, p);
        if (v > bestv){ bestv = v; bestn = p; }
    }
    if (n == 0){
        int off = (out_size > L) ? 1 : 0;
        if (off) out[0] = bestv;
        int tag = bestn;
        for (int t = L-1; t >= 0; t--){
            if (off + t < out_size) out[off + t] = (float)tag;
            tag = bp[t*T + tag];
        }
    }
}

// ---------------- launch ----------------
extern "C" void kernel_launch(void* const* d_in, const int* in_sizes, int n_in,
                              void* d_out, int out_size){
    const int*   sent   = (const int*)  d_in[0];
    const float* emb    = (const float*)d_in[1];
    const float* w_ih_f = (const float*)d_in[2];
    const float* w_hh_f = (const float*)d_in[3];
    const float* b_f    = (const float*)d_in[4];
    const float* w_ih_b = (const float*)d_in[5];
    const float* w_hh_b = (const float*)d_in[6];
    const float* b_b    = (const float*)d_in[7];
    const float* W_out  = (const float*)d_in[8];
    const float* b_out  = (const float*)d_in[9];
    const float* trans  = (const float*)d_in[10];
    const float* h0     = (const float*)d_in[11];
    const float* c0     = (const float*)d_in[12];
    float* out = (float*)d_out;

    gather_kernel<<<L, 128>>>(sent, emb);
    dim3 g2(NROW/64, L/64, 2);
    xz_gemm_kernel<<<g2, 256>>>(w_ih_f, w_ih_b, b_f, b_b);
    lstm_kernel<<<2*CSZ, LTHR>>>(w_hh_f, w_hh_b, h0, c0);
    feats_kernel<<<(L*T)/256, 256>>>(W_out, b_out);
    cudaFuncSetAttribute(viterbi_kernel, cudaFuncAttributeMaxDynamicSharedMemorySize, L*T + 1024);
    viterbi_kernel<<<1, T, L*T>>>(trans, out, out_size);
}

// round 7
// speedup vs baseline: 1.3907x; 1.3907x over previous
#include <cuda_runtime.h>
#include <cuda_bf16.h>
#include <cstdint>

#define L 4096
#define E 300
#define H2 256
#define NROW 1024         // 4*H2 gate rows
#define HID 512
#define T 16
#define START_TAG 14
#define STOP_TAG 15
#define NEGV (-10000.0f)

#define CSZ 8             // cluster size (CTAs per direction)
#define JPC (H2/CSZ)      // 32 h-indices per CTA
#define RPC (NROW/CSZ)    // 128 gate rows per CTA
#define LTHR 512          // threads per LSTM CTA

// ---------------- scratch (static device globals; no allocation) ----------------
__device__ float g_X[L*E];             // gathered embeddings   [4096,300]
__device__ float g_xz[2][L][NROW];     // x@W_ih^T + b          per dir
__device__ float g_hs[2][L][H2];       // hf / hb outputs
__device__ float g_feats[L*T];         // emission scores
__device__ float g_dummy[32];          // dummy-kernel sink (launch-index shifter)

// ---------------- helpers ----------------
__device__ __forceinline__ float sigm(float x){
    return __fdividef(1.0f, 1.0f + __expf(-x));
}
__device__ __forceinline__ float tanh_(float x){
    float ax = fabsf(x);
    float e  = __expf(-2.0f*ax);
    float t  = __fdividef(1.0f - e, 1.0f + e);
    return copysignf(t, x);
}
__device__ __forceinline__ unsigned smem_u32(const void* p){
    unsigned r;
    asm("{ .reg .u64 t; cvta.to.shared.u64 t, %1; cvt.u32.u64 %0, t; }" : "=r"(r) : "l"(p));
    return r;
}
__device__ __forceinline__ void cluster_sync_(){
    asm volatile("barrier.cluster.arrive.aligned;" ::: "memory");
    asm volatile("barrier.cluster.wait.aligned;"   ::: "memory");
}

// ---------------- 0. dummy kernel: shifts lstm into the ncu -s 5 capture slot ----------------
__global__ void dummy_kernel(){
    g_dummy[threadIdx.x] = 0.f;
}

// ---------------- 1. gather embeddings ----------------
__global__ void gather_kernel(const int* __restrict__ sent, const float* __restrict__ emb){
    int t = blockIdx.x;
    int row = sent[t];
    for (int e = threadIdx.x; e < E; e += blockDim.x)
        g_X[t*E + e] = emb[row*E + e];
}

// ---------------- 2. xz = X @ W_ih^T + b  (both directions) ----------------
#define KT 16
__global__ void __launch_bounds__(256) xz_gemm_kernel(
    const float* __restrict__ wf, const float* __restrict__ wb,
    const float* __restrict__ bf, const float* __restrict__ bb)
{
    __shared__ float As[64][20];   // pad 20 to dodge bank conflicts
    __shared__ float Bs[64][20];
    int d  = blockIdx.z;
    const float* wih  = d ? wb : wf;
    const float* bias = d ? bb : bf;
    int t0 = blockIdx.y * 64;
    int r0 = blockIdx.x * 64;
    int tid = threadIdx.x;
    int tx = tid & 15, ty = tid >> 4;
    float acc[4][4] = {};
    for (int kb = 0; kb < E; kb += KT){
        for (int idx = tid; idx < 64*KT; idx += 256){
            int row = idx >> 4, k = idx & 15;
            int kk = kb + k;
            As[row][k] = (kk < E) ? g_X[(t0+row)*E + kk]    : 0.f;
            Bs[row][k] = (kk < E) ? wih[(r0+row)*E + kk]    : 0.f;
        }
        __syncthreads();
        #pragma unroll
        for (int k4 = 0; k4 < KT; k4 += 4){
            float4 a[4], b[4];
            #pragma unroll
            for (int i=0;i<4;i++) a[i] = *(const float4*)&As[ty*4+i][k4];
            #pragma unroll
            for (int j=0;j<4;j++) b[j] = *(const float4*)&Bs[tx*4+j][k4];
            #pragma unroll
            for (int i=0;i<4;i++)
                #pragma unroll
                for (int j=0;j<4;j++)
                    acc[i][j] += a[i].x*b[j].x + a[i].y*b[j].y + a[i].z*b[j].z + a[i].w*b[j].w;
        }
        __syncthreads();
    }
    #pragma unroll
    for (int i=0;i<4;i++){
        int t = t0 + ty*4 + i;
        #pragma unroll
        for (int j=0;j<4;j++){
            int r = r0 + tx*4 + j;
            g_xz[d][t][r] = acc[i][j] + bias[r];
        }
    }
}

// ---------------- 3. sequential BiLSTM: 2 clusters of 8 CTAs (R1 structure) ----------------
__global__ void __cluster_dims__(CSZ,1,1) __launch_bounds__(LTHR,1)
lstm_kernel(const float* __restrict__ w_hh_f, const float* __restrict__ w_hh_b,
            const float* __restrict__ h0, const float* __restrict__ c0)
{
    __shared__ float h_buf[2][H2];
    __shared__ float z_s[RPC];

    unsigned rank;
    asm("mov.u32 %0, %%cluster_ctarank;" : "=r"(rank));
    int dir = blockIdx.x / CSZ;
    int tid = threadIdx.x;
    int r  = tid >> 2;          // local gate row 0..127
    int q  = tid & 3;           // quarter of the 256-wide dot
    int g  = r >> 5;            // gate 0..3 (i,f,g,o)
    int jl = r & 31;            // h-index within CTA
    int grow = g*H2 + (int)rank*JPC + jl;   // global gate row

    const float* W = (dir ? w_hh_b : w_hh_f) + grow*H2 + q*64;
    unsigned long long w2[32];                 // 64 weights as f32x2 pairs
    #pragma unroll
    for (int i=0;i<32;i++) w2[i] = ((const unsigned long long*)W)[i];

    for (int i = tid; i < H2; i += LTHR) h_buf[0][i] = h0[dir*H2 + i];
    float c = 0.f;
    if (tid < JPC) c = c0[dir*H2 + (int)rank*JPC + tid];

    const float* xz = &g_xz[dir][0][0];
    float x_cur = 0.f, x_next = 0.f;
    if (q == 0){
        int t0 = dir ? (L-1) : 0;
        x_cur = __ldg(&xz[t0*NROW + grow]);
    }
    unsigned laddr0 = smem_u32(&h_buf[0][(int)rank*JPC]);
    unsigned laddr1 = smem_u32(&h_buf[1][(int)rank*JPC]);
    __syncthreads();
    cluster_sync_();

    for (int s = 0; s < L; s++){
        int cur = s & 1;
        int nxt = cur ^ 1;
        if (q == 0 && s + 1 < L){                    // prefetch next xz (DRAM)
            int t1 = dir ? (L-2-s) : (s+1);
            x_next = __ldg(&xz[t1*NROW + grow]);
        }
        const ulonglong2* hp = (const ulonglong2*)&h_buf[cur][q*64];
        unsigned long long a0 = 0ull, a1 = 0ull;    // f32x2 accumulators
        #pragma unroll
        for (int i=0;i<16;i++){
            ulonglong2 hh = hp[i];
            asm("fma.rn.f32x2 %0, %1, %2, %0;" : "+l"(a0) : "l"(w2[2*i]),   "l"(hh.x));
            asm("fma.rn.f32x2 %0, %1, %2, %0;" : "+l"(a1) : "l"(w2[2*i+1]), "l"(hh.y));
        }
        float part = __uint_as_float((unsigned)a0) + __uint_as_float((unsigned)(a0>>32))
                   + __uint_as_float((unsigned)a1) + __uint_as_float((unsigned)(a1>>32));
        part += __shfl_xor_sync(0xffffffffu, part, 1);
        part += __shfl_xor_sync(0xffffffffu, part, 2);
        if (q == 0) z_s[r] = part + x_cur;
        __syncthreads();
        if (tid < JPC){
            float zi = z_s[tid], zf = z_s[JPC+tid], zg = z_s[2*JPC+tid], zo = z_s[3*JPC+tid];
            float ig = sigm(zi), fg = sigm(zf), og = sigm(zo);
            float gg = tanh_(zg);
            c = fg*c + ig*gg;
            float h = og * tanh_(c);
            int t_act = dir ? (L-1-s) : s;
            g_hs[dir][t_act][(int)rank*JPC + tid] = h;
            unsigned la = (nxt ? laddr1 : laddr0) + (unsigned)tid*4u;
            #pragma unroll
            for (int ct = 0; ct < CSZ; ct++){
                unsigned ra;
                asm("mapa.shared::cluster.u32 %0, %1, %2;" : "=r"(ra) : "r"(la), "r"(ct));
                asm volatile("st.shared::cluster.f32 [%0], %1;" :: "r"(ra), "f"(h));
            }
        }
        x_cur = x_next;
        cluster_sync_();   // publishes h_buf[nxt] cluster-wide (release/acquire)
    }
}

// ---------------- 4. emission features: feats = [hf|hb] @ W_out^T + b_out ----------------
__global__ void feats_kernel(const float* __restrict__ Wout, const float* __restrict__ bout){
    int gid = blockIdx.x*blockDim.x + threadIdx.x;
    int t = gid >> 4, n = gid & 15;
    const float4* hf = (const float4*)g_hs[0][t];
    const float4* hb = (const float4*)g_hs[1][t];
    const float4* w0 = (const float4*)(Wout + n*HID);
    const float4* w1 = (const float4*)(Wout + n*HID + H2);
    float acc = bout[n];
    #pragma unroll 4
    for (int k=0;k<H2/4;k++){
        float4 a = hf[k], b = w0[k];
        acc += a.x*b.x + a.y*b.y + a.z*b.z + a.w*b.w;
    }
    #pragma unroll 4
    for (int k=0;k<H2/4;k++){
        float4 a = hb[k], b = w1[k];
        acc += a.x*b.x + a.y*b.y + a.z*b.z + a.w*b.w;
    }
    g_feats[t*T + n] = acc;
}

// ---------------- 5. Viterbi + backtrack (argmax tree, backpointers in shared) ----------------
__global__ void viterbi_kernel(const float* __restrict__ trans, float* __restrict__ out,
                               int out_size){
    extern __shared__ unsigned char bp[];   // [L][T] backpointers
    int n = threadIdx.x;                    // 16 threads
    const unsigned mask = 0xffffu;
    float tr[T];
    #pragma unroll
    for (int p=0;p<T;p++) tr[p] = trans[n*T + p];   // trans[next=n][prev=p]
    float fv = (n == START_TAG) ? 0.f : NEGV;
    float f_cur = g_feats[n];
    for (int t = 0; t < L; t++){
        float f_next = (t+1 < L) ? __ldg(&g_feats[(t+1)*T + n]) : 0.f;
        float cv[T]; int ci[T];
        #pragma unroll
        for (int p=0;p<T;p++){
            cv[p] = __shfl_sync(mask, fv, p) + tr[p];
            ci[p] = p;
        }
        // argmax tree; ties keep lower index => first max, matches jnp.argmax
        #pragma unroll
        for (int w=8; w>=1; w>>=1)
            #pragma unroll
            for (int p=0;p<16;p++) if (p < w){
                if (cv[p+w] > cv[p]){ cv[p] = cv[p+w]; ci[p] = ci[p+w]; }
            }
        fv = cv[0] + f_cur;
        bp[t*T + n] = (unsigned char)ci[0];
        f_cur = f_next;
    }
    float term = fv + trans[STOP_TAG*T + n];
    __syncwarp(mask);
    float bestv = -3.4e38f; int bestn = 0;
    #pragma unroll
    for (int p=0;p<T;p++){
        float v = __shfl_sync(mask, term, p);
        if (v > bestv){ bestv = v; bestn = p; }
    }
    if (n == 0){
        int off = (out_size > L) ? 1 : 0;
        if (off) out[0] = bestv;
        int tag = bestn;
        for (int t = L-1; t >= 0; t--){
            if (off + t < out_size) out[off + t] = (float)tag;
            tag = bp[t*T + tag];
        }
    }
}

// ---------------- launch ----------------
extern "C" void kernel_launch(void* const* d_in, const int* in_sizes, int n_in,
                              void* d_out, int out_size){
    const int*   sent   = (const int*)  d_in[0];
    const float* emb    = (const float*)d_in[1];
    const float* w_ih_f = (const float*)d_in[2];
    const float* w_hh_f = (const float*)d_in[3];
    const float* b_f    = (const float*)d_in[4];
    const float* w_ih_b = (const float*)d_in[5];
    const float* w_hh_b = (const float*)d_in[6];
    const float* b_b    = (const float*)d_in[7];
    const float* W_out  = (const float*)d_in[8];
    const float* b_out  = (const float*)d_in[9];
    const float* trans  = (const float*)d_in[10];
    const float* h0     = (const float*)d_in[11];
    const float* c0     = (const float*)d_in[12];
    float* out = (float*)d_out;

    gather_kernel<<<L, 128>>>(sent, emb);
    dim3 g2(NROW/64, L/64, 2);
    xz_gemm_kernel<<<g2, 256>>>(w_ih_f, w_ih_b, b_f, b_b);
    dummy_kernel<<<1, 32>>>();                 // shifts lstm into ncu's -s 5 slot
    lstm_kernel<<<2*CSZ, LTHR>>>(w_hh_f, w_hh_b, h0, c0);
    feats_kernel<<<(L*T)/256, 256>>>(W_out, b_out);
    cudaFuncSetAttribute(viterbi_kernel, cudaFuncAttributeMaxDynamicSharedMemorySize, L*T + 1024);
    viterbi_kernel<<<1, T, L*T>>>(trans, out, out_size);
}

// round 8
// speedup vs baseline: 2.7791x; 1.9984x over previous
#include <cuda_runtime.h>
#include <cuda_bf16.h>
#include <cstdint>

#define L 4096
#define E 300
#define H2 256
#define NROW 1024         // 4*H2 gate rows
#define HID 512
#define T 16
#define START_TAG 14
#define STOP_TAG 15
#define NEGV (-10000.0f)

#define CSZ 8             // cluster size (CTAs per direction)
#define JPC (H2/CSZ)      // 32 h-indices per CTA
#define RPC (NROW/CSZ)    // 128 gate rows per CTA
#define LTHR 512          // threads per LSTM CTA

// ---------------- scratch (static device globals; no allocation) ----------------
__device__ float g_X[L*E];             // gathered embeddings   [4096,300]
__device__ float g_xz[2][L][NROW];     // x@W_ih^T + b          per dir
__device__ float g_hs[2][L][H2];       // hf / hb outputs
__device__ float g_feats[L*T];         // emission scores
__device__ float g_dummy[32];          // dummy-kernel sink (launch-index shifter)

// ---------------- helpers ----------------
__device__ __forceinline__ float sigm(float x){
    return __fdividef(1.0f, 1.0f + __expf(-x));
}
__device__ __forceinline__ float tanh_(float x){
    float ax = fabsf(x);
    float e  = __expf(-2.0f*ax);
    float t  = __fdividef(1.0f - e, 1.0f + e);
    return copysignf(t, x);
}
__device__ __forceinline__ unsigned smem_u32(const void* p){
    unsigned r;
    asm("{ .reg .u64 t; cvta.to.shared.u64 t, %1; cvt.u32.u64 %0, t; }" : "=r"(r) : "l"(p));
    return r;
}
__device__ __forceinline__ void cluster_sync_(){
    asm volatile("barrier.cluster.arrive.aligned;" ::: "memory");
    asm volatile("barrier.cluster.wait.aligned;"   ::: "memory");
}

// ---------------- 0. dummy kernel: keeps lstm in the ncu capture slot ----------------
__global__ void dummy_kernel(){
    g_dummy[threadIdx.x] = 0.f;
}

// ---------------- 1. gather embeddings ----------------
__global__ void gather_kernel(const int* __restrict__ sent, const float* __restrict__ emb){
    int t = blockIdx.x;
    int row = sent[t];
    for (int e = threadIdx.x; e < E; e += blockDim.x)
        g_X[t*E + e] = emb[row*E + e];
}

// ---------------- 2. xz = X @ W_ih^T + b  (both directions) ----------------
#define KT 16
__global__ void __launch_bounds__(256) xz_gemm_kernel(
    const float* __restrict__ wf, const float* __restrict__ wb,
    const float* __restrict__ bf, const float* __restrict__ bb)
{
    __shared__ float As[64][20];   // pad 20 to dodge bank conflicts
    __shared__ float Bs[64][20];
    int d  = blockIdx.z;
    const float* wih  = d ? wb : wf;
    const float* bias = d ? bb : bf;
    int t0 = blockIdx.y * 64;
    int r0 = blockIdx.x * 64;
    int tid = threadIdx.x;
    int tx = tid & 15, ty = tid >> 4;
    float acc[4][4] = {};
    for (int kb = 0; kb < E; kb += KT){
        for (int idx = tid; idx < 64*KT; idx += 256){
            int row = idx >> 4, k = idx & 15;
            int kk = kb + k;
            As[row][k] = (kk < E) ? g_X[(t0+row)*E + kk]    : 0.f;
            Bs[row][k] = (kk < E) ? wih[(r0+row)*E + kk]    : 0.f;
        }
        __syncthreads();
        #pragma unroll
        for (int k4 = 0; k4 < KT; k4 += 4){
            float4 a[4], b[4];
            #pragma unroll
            for (int i=0;i<4;i++) a[i] = *(const float4*)&As[ty*4+i][k4];
            #pragma unroll
            for (int j=0;j<4;j++) b[j] = *(const float4*)&Bs[tx*4+j][k4];
            #pragma unroll
            for (int i=0;i<4;i++)
                #pragma unroll
                for (int j=0;j<4;j++)
                    acc[i][j] += a[i].x*b[j].x + a[i].y*b[j].y + a[i].z*b[j].z + a[i].w*b[j].w;
        }
        __syncthreads();
    }
    #pragma unroll
    for (int i=0;i<4;i++){
        int t = t0 + ty*4 + i;
        #pragma unroll
        for (int j=0;j<4;j++){
            int r = r0 + tx*4 + j;
            g_xz[d][t][r] = acc[i][j] + bias[r];
        }
    }
}

// ---------------- 3. sequential BiLSTM: 2 clusters of 8 CTAs ----------------
// Interleaved K-slices: thread q reads h chunks c = 4i+q (16B each).  Within a
// warp the 8 row-lanes broadcast-dedup and the 4 q-lanes are bank-disjoint ->
// conflict-free LDS.128 (old blocked layout was 4-way conflicted every load).
// Weights permuted identically at the one-time register load.
__global__ void __cluster_dims__(CSZ,1,1) __launch_bounds__(LTHR,1)
lstm_kernel(const float* __restrict__ w_hh_f, const float* __restrict__ w_hh_b,
            const float* __restrict__ h0, const float* __restrict__ c0)
{
    __shared__ alignas(16) float h_buf[2][H2];
    __shared__ float z_s[RPC];

    unsigned rank;
    asm("mov.u32 %0, %%cluster_ctarank;" : "=r"(rank));
    int dir = blockIdx.x / CSZ;
    int tid = threadIdx.x;
    int r  = tid >> 2;          // local gate row 0..127
    int q  = tid & 3;           // quarter of the 256-wide dot (interleaved)
    int g  = r >> 5;            // gate 0..3 (i,f,g,o)
    int jl = r & 31;            // h-index within CTA
    int grow = g*H2 + (int)rank*JPC + jl;   // global gate row

    // interleaved weight load: w2[2i],w2[2i+1] cover h[16i+4q .. 16i+4q+3]
    const unsigned long long* Wp =
        (const unsigned long long*)((dir ? w_hh_b : w_hh_f) + grow*H2);
    unsigned long long w2[32];
    #pragma unroll
    for (int i=0;i<16;i++){
        w2[2*i]   = Wp[8*i + 2*q];
        w2[2*i+1] = Wp[8*i + 2*q + 1];
    }

    for (int i = tid; i < H2; i += LTHR) h_buf[0][i] = h0[dir*H2 + i];
    float c = 0.f;
    if (tid < JPC) c = c0[dir*H2 + (int)rank*JPC + tid];

    const float* xz = &g_xz[dir][0][0];
    float x_cur = 0.f, x_next = 0.f;
    if (q == 0){
        int t0 = dir ? (L-1) : 0;
        x_cur = __ldg(&xz[t0*NROW + grow]);
    }

    // hoisted remote store addresses (tid<32 activation role), buffer 0
    unsigned ra[CSZ];
    {
        unsigned la = smem_u32(&h_buf[0][(int)rank*JPC]) + (unsigned)(tid & 31)*4u;
        #pragma unroll
        for (int ct = 0; ct < CSZ; ct++)
            asm("mapa.shared::cluster.u32 %0, %1, %2;" : "=r"(ra[ct]) : "r"(la), "r"(ct));
    }

    __syncthreads();
    cluster_sync_();

    const char* hbase = (const char*)&h_buf[0][0];

    for (int s = 0; s < L; s++){
        int cur = s & 1;
        int nxt = cur ^ 1;
        if (q == 0 && s + 1 < L){                    // prefetch next xz (DRAM/L2)
            int t1 = dir ? (L-2-s) : (s+1);
            x_next = __ldg(&xz[t1*NROW + grow]);
        }
        const char* hb = hbase + cur*(H2*4) + q*16;
        unsigned long long a0 = 0ull, a1 = 0ull;    // f32x2 accumulators
        #pragma unroll
        for (int i=0;i<16;i++){
            ulonglong2 hh = *(const ulonglong2*)(hb + i*64);
            asm("fma.rn.f32x2 %0, %1, %2, %0;" : "+l"(a0) : "l"(w2[2*i]),   "l"(hh.x));
            asm("fma.rn.f32x2 %0, %1, %2, %0;" : "+l"(a1) : "l"(w2[2*i+1]), "l"(hh.y));
        }
        float part = __uint_as_float((unsigned)a0) + __uint_as_float((unsigned)(a0>>32))
                   + __uint_as_float((unsigned)a1) + __uint_as_float((unsigned)(a1>>32));
        part += __shfl_xor_sync(0xffffffffu, part, 1);
        part += __shfl_xor_sync(0xffffffffu, part, 2);
        if (q == 0) z_s[r] = part + x_cur;
        __syncthreads();
        if (tid < JPC){
            float zi = z_s[tid], zf = z_s[JPC+tid], zg = z_s[2*JPC+tid], zo = z_s[3*JPC+tid];
            float ig = sigm(zi), fg = sigm(zf), og = sigm(zo);
            float gg = tanh_(zg);
            c = fg*c + ig*gg;
            float h = og * tanh_(c);
            unsigned doff = (unsigned)nxt * (H2*4u);
            #pragma unroll
            for (int ct = 0; ct < CSZ; ct++)
                asm volatile("st.shared::cluster.f32 [%0], %1;"
                             :: "r"(ra[ct] + doff), "f"(h));
            int t_act = dir ? (L-1-s) : s;
            g_hs[dir][t_act][(int)rank*JPC + tid] = h;
        }
        x_cur = x_next;
        cluster_sync_();   // publishes h_buf[nxt] cluster-wide (release/acquire)
    }
}

// ---------------- 4. emission features: feats = [hf|hb] @ W_out^T + b_out ----------------
__global__ void feats_kernel(const float* __restrict__ Wout, const float* __restrict__ bout){
    int gid = blockIdx.x*blockDim.x + threadIdx.x;
    int t = gid >> 4, n = gid & 15;
    const float4* hf = (const float4*)g_hs[0][t];
    const float4* hb = (const float4*)g_hs[1][t];
    const float4* w0 = (const float4*)(Wout + n*HID);
    const float4* w1 = (const float4*)(Wout + n*HID + H2);
    float acc = bout[n];
    #pragma unroll 4
    for (int k=0;k<H2/4;k++){
        float4 a = hf[k], b = w0[k];
        acc += a.x*b.x + a.y*b.y + a.z*b.z + a.w*b.w;
    }
    #pragma unroll 4
    for (int k=0;k<H2/4;k++){
        float4 a = hb[k], b = w1[k];
        acc += a.x*b.x + a.y*b.y + a.z*b.z + a.w*b.w;
    }
    g_feats[t*T + n] = acc;
}

// ---------------- 5. Viterbi + backtrack (argmax tree, backpointers in shared) ----------------
__global__ void viterbi_kernel(const float* __restrict__ trans, float* __restrict__ out,
                               int out_size){
    extern __shared__ unsigned char bp[];   // [L][T] backpointers
    int n = threadIdx.x;                    // 16 threads
    const unsigned mask = 0xffffu;
    float tr[T];
    #pragma unroll
    for (int p=0;p<T;p++) tr[p] = trans[n*T + p];   // trans[next=n][prev=p]
    float fv = (n == START_TAG) ? 0.f : NEGV;
    float f_cur = g_feats[n];
    for (int t = 0; t < L; t++){
        float f_next = (t+1 < L) ? __ldg(&g_feats[(t+1)*T + n]) : 0.f;
        float cv[T]; int ci[T];
        #pragma unroll
        for (int p=0;p<T;p++){
            cv[p] = __shfl_sync(mask, fv, p) + tr[p];
            ci[p] = p;
        }
        // argmax tree; ties keep lower index => first max, matches jnp.argmax
        #pragma unroll
        for (int w=8; w>=1; w>>=1)
            #pragma unroll
            for (int p=0;p<16;p++) if (p < w){
                if (cv[p+w] > cv[p]){ cv[p] = cv[p+w]; ci[p] = ci[p+w]; }
            }
        fv = cv[0] + f_cur;
        bp[t*T + n] = (unsigned char)ci[0];
        f_cur = f_next;
    }
    float term = fv + trans[STOP_TAG*T + n];
    __syncwarp(mask);
    float bestv = -3.4e38f; int bestn = 0;
    #pragma unroll
    for (int p=0;p<T;p++){
        float v = __shfl_sync(mask, term, p);
        if (v > bestv){ bestv = v; bestn = p; }
    }
    if (n == 0){
        int off = (out_size > L) ? 1 : 0;
        if (off) out[0] = bestv;
        int tag = bestn;
        for (int t = L-1; t >= 0; t--){
            if (off + t < out_size) out[off + t] = (float)tag;
            tag = bp[t*T + tag];
        }
    }
}

// ---------------- launch ----------------
extern "C" void kernel_launch(void* const* d_in, const int* in_sizes, int n_in,
                              void* d_out, int out_size){
    const int*   sent   = (const int*)  d_in[0];
    const float* emb    = (const float*)d_in[1];
    const float* w_ih_f = (const float*)d_in[2];
    const float* w_hh_f = (const float*)d_in[3];
    const float* b_f    = (const float*)d_in[4];
    const float* w_ih_b = (const float*)d_in[5];
    const float* w_hh_b = (const float*)d_in[6];
    const float* b_b    = (const float*)d_in[7];
    const float* W_out  = (const float*)d_in[8];
    const float* b_out  = (const float*)d_in[9];
    const float* trans  = (const float*)d_in[10];
    const float* h0     = (const float*)d_in[11];
    const float* c0     = (const float*)d_in[12];
    float* out = (float*)d_out;

    gather_kernel<<<L, 128>>>(sent, emb);
    dim3 g2(NROW/64, L/64, 2);
    xz_gemm_kernel<<<g2, 256>>>(w_ih_f, w_ih_b, b_f, b_b);
    dummy_kernel<<<1, 32>>>();                 // keeps lstm in ncu's capture slot
    lstm_kernel<<<2*CSZ, LTHR>>>(w_hh_f, w_hh_b, h0, c0);
    feats_kernel<<<(L*T)/256, 256>>>(W_out, b_out);
    cudaFuncSetAttribute(viterbi_kernel, cudaFuncAttributeMaxDynamicSharedMemorySize, L*T + 1024);
    viterbi_kernel<<<1, T, L*T>>>(trans, out, out_size);
}